// round 2
// baseline (speedup 1.0000x reference)
#include <cuda_runtime.h>

#define B_SZ 8192
#define M_SZ 64
#define D_SZ 256

// scratch for r = attn-weighted memory readout  [B, D]
__device__ float g_r[B_SZ * D_SZ];

// ---------------------------------------------------------------------------
// Kernel A: per-sample ragged attention -> r
// grid = B, block = 256 threads, dynamic smem = mem tile + h + attn
// ---------------------------------------------------------------------------
__global__ __launch_bounds__(256, 3)
void attn_r_kernel(const float* __restrict__ h_tilde,
                   const float* __restrict__ mem,
                   const int* __restrict__ lengths) {
    extern __shared__ float smem[];
    float* s_mem  = smem;                  // 64*256 floats (64 KB)
    float* s_h    = smem + M_SZ * D_SZ;    // 256
    float* s_attn = s_h + D_SZ;            // 64

    const int b   = blockIdx.x;
    const int tid = threadIdx.x;

    // load h_tilde row
    s_h[tid] = h_tilde[(size_t)b * D_SZ + tid];

    // cooperative float4 load of mem[b] into smem (read from HBM exactly once)
    const float4* g4 = (const float4*)(mem + (size_t)b * M_SZ * D_SZ);
    float4* s4 = (float4*)s_mem;
#pragma unroll
    for (int i = 0; i < 16; ++i)
        s4[tid + 256 * i] = g4[tid + 256 * i];
    __syncthreads();

    const int warp = tid >> 5;
    const int lane = tid & 31;
    const int len  = lengths[b];

    // scores: warp w handles rows 8w..8w+7
#pragma unroll
    for (int j = 0; j < 8; ++j) {
        const int m = warp * 8 + j;
        const float* row = s_mem + m * D_SZ;
        float acc = 0.f;
#pragma unroll
        for (int k = 0; k < 8; ++k) {
            const int d = lane + 32 * k;
            acc = fmaf(row[d], s_h[d], acc);
        }
#pragma unroll
        for (int off = 16; off; off >>= 1)
            acc += __shfl_xor_sync(0xffffffffu, acc, off);
        if (lane == j)
            s_attn[m] = (m < len) ? acc : -1e9f;
    }
    __syncthreads();

    // softmax over 64 masked scores (warp 0, 2 values per lane)
    if (warp == 0) {
        float v0 = s_attn[lane];
        float v1 = s_attn[lane + 32];
        float mx = fmaxf(v0, v1);
#pragma unroll
        for (int off = 16; off; off >>= 1)
            mx = fmaxf(mx, __shfl_xor_sync(0xffffffffu, mx, off));
        float e0 = __expf(v0 - mx);
        float e1 = __expf(v1 - mx);
        float s = e0 + e1;
#pragma unroll
        for (int off = 16; off; off >>= 1)
            s += __shfl_xor_sync(0xffffffffu, s, off);
        float inv = 1.f / s;
        s_attn[lane]      = e0 * inv;
        s_attn[lane + 32] = e1 * inv;
    }
    __syncthreads();

    // r[d] = sum_m attn[m] * mem[m][d]; thread owns column d = tid
    float acc = 0.f;
#pragma unroll
    for (int m = 0; m < M_SZ; ++m)
        acc = fmaf(s_attn[m], s_mem[m * D_SZ + tid], acc);
    g_r[(size_t)b * D_SZ + tid] = acc;
}

// ---------------------------------------------------------------------------
// Kernel B: gate GEMM Z = [h|r] @ [Wg|Ug]^T + bias, sigmoid, fuse, mask
// Tiled fp32 GEMM: BM=64 (samples), BN=64 (out dims), BK=32, K=512.
// 256 threads, 4x4 register tile per thread.
// ---------------------------------------------------------------------------
#define BMt 64
#define BNt 64
#define BKt 32
#define LDT 68   // padded stride for k-major smem tiles (16B aligned, de-conflicted)

__global__ __launch_bounds__(256)
void gate_gemm_kernel(const float* __restrict__ h_tilde,
                      const float* __restrict__ Wg_w,
                      const float* __restrict__ Ug_w,
                      const float* __restrict__ Wg_b,
                      const float* __restrict__ Ug_b,
                      const float* __restrict__ b_g,
                      const int* __restrict__ lengths,
                      float* __restrict__ out) {
    __shared__ float sA[BKt * LDT];   // X tile, k-major:  sA[k*LDT + m]
    __shared__ float sB[BKt * LDT];   // W tile, k-major:  sB[k*LDT + n]

    const int tid = threadIdx.x;
    const int bm0 = blockIdx.x * BMt;
    const int gn0 = blockIdx.y * BNt;
    const int tx  = tid & 15;    // n sub-tile (4 cols)
    const int ty  = tid >> 4;    // m sub-tile (4 rows)

    const int lrow = tid >> 2;   // 0..63 : loader row
    const int lc   = tid & 3;    // loader float4 col base

    float acc[4][4] = {};

    const float* r_ptr = g_r;

    for (int kt = 0; kt < 16; ++kt) {
        const int k0 = kt * BKt;
        const float* Xsrc = (k0 < 256)
            ? (h_tilde + (size_t)bm0 * D_SZ + k0)
            : (r_ptr   + (size_t)bm0 * D_SZ + (k0 - 256));
        const float* Wsrc = (k0 < 256)
            ? (Wg_w + (size_t)gn0 * D_SZ + k0)
            : (Ug_w + (size_t)gn0 * D_SZ + (k0 - 256));

        __syncthreads();
#pragma unroll
        for (int hh = 0; hh < 2; ++hh) {
            const int c = lc + 4 * hh;   // 0..7 -> k sub-cols 4c..4c+3
            float4 va = *(const float4*)(Xsrc + (size_t)lrow * D_SZ + 4 * c);
            float4 vb = *(const float4*)(Wsrc + (size_t)lrow * D_SZ + 4 * c);
            sA[(4 * c + 0) * LDT + lrow] = va.x;
            sA[(4 * c + 1) * LDT + lrow] = va.y;
            sA[(4 * c + 2) * LDT + lrow] = va.z;
            sA[(4 * c + 3) * LDT + lrow] = va.w;
            sB[(4 * c + 0) * LDT + lrow] = vb.x;
            sB[(4 * c + 1) * LDT + lrow] = vb.y;
            sB[(4 * c + 2) * LDT + lrow] = vb.z;
            sB[(4 * c + 3) * LDT + lrow] = vb.w;
        }
        __syncthreads();

#pragma unroll
        for (int k = 0; k < BKt; ++k) {
            float4 a  = *(const float4*)(sA + k * LDT + 4 * ty);
            float4 bb = *(const float4*)(sB + k * LDT + 4 * tx);
            acc[0][0] = fmaf(a.x, bb.x, acc[0][0]);
            acc[0][1] = fmaf(a.x, bb.y, acc[0][1]);
            acc[0][2] = fmaf(a.x, bb.z, acc[0][2]);
            acc[0][3] = fmaf(a.x, bb.w, acc[0][3]);
            acc[1][0] = fmaf(a.y, bb.x, acc[1][0]);
            acc[1][1] = fmaf(a.y, bb.y, acc[1][1]);
            acc[1][2] = fmaf(a.y, bb.z, acc[1][2]);
            acc[1][3] = fmaf(a.y, bb.w, acc[1][3]);
            acc[2][0] = fmaf(a.z, bb.x, acc[2][0]);
            acc[2][1] = fmaf(a.z, bb.y, acc[2][1]);
            acc[2][2] = fmaf(a.z, bb.z, acc[2][2]);
            acc[2][3] = fmaf(a.z, bb.w, acc[2][3]);
            acc[3][0] = fmaf(a.w, bb.x, acc[3][0]);
            acc[3][1] = fmaf(a.w, bb.y, acc[3][1]);
            acc[3][2] = fmaf(a.w, bb.z, acc[3][2]);
            acc[3][3] = fmaf(a.w, bb.w, acc[3][3]);
        }
    }

    // epilogue: bias + sigmoid + gated fusion + empty-memory passthrough
    float bias[4];
#pragma unroll
    for (int i = 0; i < 4; ++i) {
        const int n = gn0 + 4 * tx + i;
        bias[i] = Wg_b[n] + Ug_b[n] + b_g[n];
    }
#pragma unroll
    for (int j = 0; j < 4; ++j) {
        const int row = bm0 + 4 * ty + j;
        const bool has_mem = lengths[row] > 0;
        const size_t base = (size_t)row * D_SZ + gn0 + 4 * tx;
        float4 rv = *(const float4*)(g_r + base);
        float4 hv = *(const float4*)(h_tilde + base);
        float o[4];
        const float rr[4] = {rv.x, rv.y, rv.z, rv.w};
        const float hh[4] = {hv.x, hv.y, hv.z, hv.w};
#pragma unroll
        for (int i = 0; i < 4; ++i) {
            float z = acc[j][i] + bias[i];
            float g = 1.f / (1.f + __expf(-z));
            o[i] = has_mem ? (g * rr[i] + (1.f - g) * hh[i]) : hh[i];
        }
        *(float4*)(out + base) = make_float4(o[0], o[1], o[2], o[3]);
    }
}

// ---------------------------------------------------------------------------
extern "C" void kernel_launch(void* const* d_in, const int* in_sizes, int n_in,
                              void* d_out, int out_size) {
    const float* h_tilde = (const float*)d_in[0];
    const float* mem     = (const float*)d_in[1];
    const int*   lengths = (const int*)d_in[2];
    const float* Wg_w    = (const float*)d_in[3];
    const float* Wg_b    = (const float*)d_in[4];
    const float* Ug_w    = (const float*)d_in[5];
    const float* Ug_b    = (const float*)d_in[6];
    const float* b_g     = (const float*)d_in[7];
    float* out = (float*)d_out;

    const int smem_a = (M_SZ * D_SZ + D_SZ + M_SZ) * (int)sizeof(float);  // ~66.8 KB
    cudaFuncSetAttribute(attn_r_kernel,
                         cudaFuncAttributeMaxDynamicSharedMemorySize, smem_a);

    attn_r_kernel<<<B_SZ, 256, smem_a>>>(h_tilde, mem, lengths);

    dim3 grid(B_SZ / BMt, D_SZ / BNt);   // 128 x 4
    gate_gemm_kernel<<<grid, 256>>>(h_tilde, Wg_w, Ug_w, Wg_b, Ug_b, b_g,
                                    lengths, out);
}

// round 4
// speedup vs baseline: 1.4934x; 1.4934x over previous
#include <cuda_runtime.h>
#include <cuda_bf16.h>
#include <cstdint>

#define B_SZ 8192
#define M_SZ 64
#define D_SZ 256
#define K2   1536   // [Xh | Xh | Xl] along K

// scratch (static device arrays — no allocation)
__device__ __align__(256) float          g_r[B_SZ * D_SZ];              // 8 MB
__device__ __align__(256) __nv_bfloat16  g_Xc[(size_t)B_SZ * K2];       // 24 MB
__device__ __align__(256) __nv_bfloat16  g_Wc[256 * K2];                // 768 KB

// ---------------------------------------------------------------------------
// cp.async helpers
// ---------------------------------------------------------------------------
__device__ __forceinline__ void cp_async16(void* smem_ptr, const void* gptr) {
    unsigned sa = (unsigned)__cvta_generic_to_shared(smem_ptr);
    asm volatile("cp.async.cg.shared.global [%0], [%1], 16;\n" :: "r"(sa), "l"(gptr));
}
__device__ __forceinline__ void cp_commit() {
    asm volatile("cp.async.commit_group;\n");
}
template<int N> __device__ __forceinline__ void cp_wait() {
    asm volatile("cp.async.wait_group %0;\n" :: "n"(N));
}

// ---------------------------------------------------------------------------
// Kernel A: ragged attention with chunked ONLINE softmax + cp.async pipeline.
// 16-row chunks, double buffered -> ~34 KB smem -> 6 CTAs/SM.
// Also emits this sample's row of Xc = [h_hi | r_hi | h_hi | r_hi | h_lo | r_lo].
// ---------------------------------------------------------------------------
#define CH 16

__global__ __launch_bounds__(256, 6)
void attn_r_kernel(const float* __restrict__ h_tilde,
                   const float* __restrict__ mem,
                   const int* __restrict__ lengths) {
    __shared__ __align__(16) float buf[2][CH * D_SZ];   // 2 x 16 KB
    __shared__ float s_h[D_SZ];
    __shared__ float s_sc[CH];
    __shared__ float s_w[CH];
    __shared__ float s_corr;
    __shared__ float s_S;

    const int b    = blockIdx.x;
    const int tid  = threadIdx.x;
    const int warp = tid >> 5;
    const int lane = tid & 31;
    const int len  = lengths[b];

    s_h[tid] = h_tilde[(size_t)b * D_SZ + tid];
    const float* gm = mem + (size_t)b * M_SZ * D_SZ;

    // prefetch chunk 0
    {
        const float4* g4 = (const float4*)gm;
        float4* s4 = (float4*)buf[0];
#pragma unroll
        for (int i = 0; i < 4; ++i)
            cp_async16(s4 + tid + 256 * i, g4 + tid + 256 * i);
        cp_commit();
    }

    float racc = 0.f;
    float Mrun = -3.0e38f;   // maintained coherently by warp 0
    float Srun = 0.f;

#pragma unroll
    for (int c = 0; c < 4; ++c) {
        if (c < 3) {
            const float4* g4 = (const float4*)(gm + (c + 1) * CH * D_SZ);
            float4* s4 = (float4*)buf[(c + 1) & 1];
#pragma unroll
            for (int i = 0; i < 4; ++i)
                cp_async16(s4 + tid + 256 * i, g4 + tid + 256 * i);
            cp_commit();
            cp_wait<1>();          // chunk c arrived; c+1 may still fly
        } else {
            cp_wait<0>();
        }
        __syncthreads();

        const float* bm = buf[c & 1];

        // scores: warp w -> local rows 2w, 2w+1
#pragma unroll
        for (int j = 0; j < 2; ++j) {
            const int mrow = warp * 2 + j;
            const float* row = bm + mrow * D_SZ;
            float acc = 0.f;
#pragma unroll
            for (int k = 0; k < 8; ++k)
                acc = fmaf(row[lane + 32 * k], s_h[lane + 32 * k], acc);
#pragma unroll
            for (int off = 16; off; off >>= 1)
                acc += __shfl_xor_sync(0xffffffffu, acc, off);
            if (lane == 0)
                s_sc[mrow] = (c * CH + mrow < len) ? acc : -1e9f;
        }
        __syncthreads();

        // online softmax merge (warp 0)
        if (warp == 0) {
            float v = (lane < CH) ? s_sc[lane] : -3.0e38f;
            float cmax = v;
#pragma unroll
            for (int off = 16; off; off >>= 1)
                cmax = fmaxf(cmax, __shfl_xor_sync(0xffffffffu, cmax, off));
            float nM   = fmaxf(Mrun, cmax);
            float corr = __expf(Mrun - nM);
            float e    = (lane < CH) ? __expf(v - nM) : 0.f;
            float cs = e;
#pragma unroll
            for (int off = 16; off; off >>= 1)
                cs += __shfl_xor_sync(0xffffffffu, cs, off);
            Srun = Srun * corr + cs;
            Mrun = nM;
            if (lane < CH) s_w[lane] = e;
            if (lane == 0) { s_corr = corr; if (c == 3) s_S = Srun; }
        }
        __syncthreads();

        // r accumulation: thread owns column d = tid
        const float corr = s_corr;
        float acc2 = 0.f;
#pragma unroll
        for (int i = 0; i < CH; ++i)
            acc2 = fmaf(s_w[i], bm[i * D_SZ + tid], acc2);
        racc = racc * corr + acc2;
        __syncthreads();   // protects buf[c&1] before it is re-prefetched
    }

    const float r = racc / s_S;
    g_r[(size_t)b * D_SZ + tid] = r;

    // emit bf16 hi/lo split row of Xc
    const float hv = s_h[tid];
    __nv_bfloat16 hh = __float2bfloat16_rn(hv);
    __nv_bfloat16 hl = __float2bfloat16_rn(hv - __bfloat162float(hh));
    __nv_bfloat16 rh = __float2bfloat16_rn(r);
    __nv_bfloat16 rl = __float2bfloat16_rn(r - __bfloat162float(rh));
    __nv_bfloat16* xr = g_Xc + (size_t)b * K2;
    xr[tid]        = hh;
    xr[256 + tid]  = rh;
    xr[512 + tid]  = hh;
    xr[768 + tid]  = rh;
    xr[1024 + tid] = hl;
    xr[1280 + tid] = rl;
}

// ---------------------------------------------------------------------------
// W conversion: Wc[n][0:512]=hi(W), [512:1024]=lo(W), [1024:1536]=hi(W)
// where W[n] = [Wg_w[n] | Ug_w[n]]  (pairs with Xc = [Xh | Xh | Xl])
// ---------------------------------------------------------------------------
__global__ void conv_w_kernel(const float* __restrict__ Wg_w,
                              const float* __restrict__ Ug_w) {
    const int n   = blockIdx.x;
    const int tid = threadIdx.x;
#pragma unroll
    for (int i = 0; i < 6; ++i) {
        int j   = tid + 256 * i;
        int k   = j & 511;
        int seg = j >> 9;
        float w = (k < 256) ? Wg_w[n * 256 + k] : Ug_w[n * 256 + (k - 256)];
        __nv_bfloat16 hi = __float2bfloat16_rn(w);
        __nv_bfloat16 v  = (seg == 1)
            ? __float2bfloat16_rn(w - __bfloat162float(hi))
            : hi;
        g_Wc[n * K2 + j] = v;
    }
}

// ---------------------------------------------------------------------------
// Kernel B: bf16 tensor-core GEMM (K=1536) + fused epilogue.
// BM=128, BN=128, BK=32, 256 threads (8 warps 4x2, warp tile 32x64).
// Conflict-free smem via 80-byte row stride. cp.async double buffered.
// ---------------------------------------------------------------------------
#define BM 128
#define BN 128
#define BK 32
#define LDSK 40   // bf16 elements per smem row (80 bytes)

__device__ __forceinline__ void mma16816(float c[4], const uint32_t a[4],
                                         const uint32_t bq[2]) {
    asm volatile(
        "mma.sync.aligned.m16n8k16.row.col.f32.bf16.bf16.f32 "
        "{%0,%1,%2,%3}, {%4,%5,%6,%7}, {%8,%9}, {%0,%1,%2,%3};\n"
        : "+f"(c[0]), "+f"(c[1]), "+f"(c[2]), "+f"(c[3])
        : "r"(a[0]), "r"(a[1]), "r"(a[2]), "r"(a[3]), "r"(bq[0]), "r"(bq[1]));
}

__global__ __launch_bounds__(256)
void gate_gemm_bf16(const float* __restrict__ h_tilde,
                    const float* __restrict__ Wg_b,
                    const float* __restrict__ Ug_b,
                    const float* __restrict__ b_g,
                    const int* __restrict__ lengths,
                    float* __restrict__ out) {
    __shared__ __align__(16) __nv_bfloat16 sA[2][BM * LDSK];
    __shared__ __align__(16) __nv_bfloat16 sB[2][BN * LDSK];

    const int tid  = threadIdx.x;
    const int warp = tid >> 5;
    const int lane = tid & 31;
    const int g    = lane >> 2;
    const int t    = lane & 3;
    const int wm   = warp >> 1;       // 0..3
    const int wn   = warp & 1;        // 0..1
    const int bm0  = blockIdx.x * BM;
    const int bn0  = blockIdx.y * BN;

    float acc[2][8][4];
#pragma unroll
    for (int mt = 0; mt < 2; ++mt)
#pragma unroll
        for (int nt = 0; nt < 8; ++nt)
#pragma unroll
            for (int i = 0; i < 4; ++i) acc[mt][nt][i] = 0.f;

    const __nv_bfloat16* gA = g_Xc + (size_t)bm0 * K2;
    const __nv_bfloat16* gB = g_Wc + (size_t)bn0 * K2;

    const int c0r = tid >> 2, c0c = tid & 3;                 // chunk tid
    const int c1r = (tid + 256) >> 2, c1c = tid & 3;         // chunk tid+256

    // prefetch stage 0
    {
        cp_async16(&sA[0][c0r * LDSK + c0c * 8], gA + (size_t)c0r * K2 + c0c * 8);
        cp_async16(&sB[0][c0r * LDSK + c0c * 8], gB + (size_t)c0r * K2 + c0c * 8);
        cp_async16(&sA[0][c1r * LDSK + c1c * 8], gA + (size_t)c1r * K2 + c1c * 8);
        cp_async16(&sB[0][c1r * LDSK + c1c * 8], gB + (size_t)c1r * K2 + c1c * 8);
        cp_commit();
    }

    const int NKT = K2 / BK;   // 48
    for (int kt = 0; kt < NKT; ++kt) {
        __syncthreads();       // everyone done reading stage (kt+1)&1 from iter kt-1
        if (kt + 1 < NKT) {
            const int ko = (kt + 1) * BK;
            const int st = (kt + 1) & 1;
            cp_async16(&sA[st][c0r * LDSK + c0c * 8], gA + (size_t)c0r * K2 + ko + c0c * 8);
            cp_async16(&sB[st][c0r * LDSK + c0c * 8], gB + (size_t)c0r * K2 + ko + c0c * 8);
            cp_async16(&sA[st][c1r * LDSK + c1c * 8], gA + (size_t)c1r * K2 + ko + c1c * 8);
            cp_async16(&sB[st][c1r * LDSK + c1c * 8], gB + (size_t)c1r * K2 + ko + c1c * 8);
            cp_commit();
            cp_wait<1>();
        } else {
            cp_wait<0>();
        }
        __syncthreads();       // stage kt visible to all warps

        const __nv_bfloat16* A  = sA[kt & 1];
        const __nv_bfloat16* Bs = sB[kt & 1];

#pragma unroll
        for (int ks = 0; ks < 2; ++ks) {
            uint32_t af[2][4], bq[8][2];
#pragma unroll
            for (int mt = 0; mt < 2; ++mt) {
                const int idx0 = (wm * 32 + mt * 16 + g) * LDSK + ks * 16 + 2 * t;
                af[mt][0] = *(const uint32_t*)(A + idx0);
                af[mt][1] = *(const uint32_t*)(A + idx0 + 8 * LDSK);
                af[mt][2] = *(const uint32_t*)(A + idx0 + 8);
                af[mt][3] = *(const uint32_t*)(A + idx0 + 8 * LDSK + 8);
            }
#pragma unroll
            for (int nt = 0; nt < 8; ++nt) {
                const int idx = (wn * 64 + nt * 8 + g) * LDSK + ks * 16 + 2 * t;
                bq[nt][0] = *(const uint32_t*)(Bs + idx);
                bq[nt][1] = *(const uint32_t*)(Bs + idx + 8);
            }
#pragma unroll
            for (int mt = 0; mt < 2; ++mt)
#pragma unroll
                for (int nt = 0; nt < 8; ++nt)
                    mma16816(acc[mt][nt], af[mt], bq[nt]);
        }
    }

    // fused epilogue: z + bias -> sigmoid -> gate -> has_mem mask
#pragma unroll
    for (int nt = 0; nt < 8; ++nt) {
        const int n = bn0 + wn * 64 + nt * 8 + 2 * t;
        const float bi0 = Wg_b[n] + Ug_b[n] + b_g[n];
        const float bi1 = Wg_b[n + 1] + Ug_b[n + 1] + b_g[n + 1];
#pragma unroll
        for (int mt = 0; mt < 2; ++mt) {
#pragma unroll
            for (int h2 = 0; h2 < 2; ++h2) {
                const int row = bm0 + wm * 32 + mt * 16 + g + 8 * h2;
                const bool has = lengths[row] > 0;
                const size_t base = (size_t)row * D_SZ + n;
                const float2 rv = *(const float2*)(g_r + base);
                const float2 hv = *(const float2*)(h_tilde + base);
                const float z0 = acc[mt][nt][2 * h2 + 0] + bi0;
                const float z1 = acc[mt][nt][2 * h2 + 1] + bi1;
                const float g0 = 1.f / (1.f + __expf(-z0));
                const float g1 = 1.f / (1.f + __expf(-z1));
                const float o0 = has ? (g0 * rv.x + (1.f - g0) * hv.x) : hv.x;
                const float o1 = has ? (g1 * rv.y + (1.f - g1) * hv.y) : hv.y;
                *(float2*)(out + base) = make_float2(o0, o1);
            }
        }
    }
}

// ---------------------------------------------------------------------------
extern "C" void kernel_launch(void* const* d_in, const int* in_sizes, int n_in,
                              void* d_out, int out_size) {
    const float* h_tilde = (const float*)d_in[0];
    const float* mem     = (const float*)d_in[1];
    const int*   lengths = (const int*)d_in[2];
    const float* Wg_w    = (const float*)d_in[3];
    const float* Wg_b    = (const float*)d_in[4];
    const float* Ug_w    = (const float*)d_in[5];
    const float* Ug_b    = (const float*)d_in[6];
    const float* b_g     = (const float*)d_in[7];
    float* out = (float*)d_out;

    conv_w_kernel<<<256, 256>>>(Wg_w, Ug_w);
    attn_r_kernel<<<B_SZ, 256>>>(h_tilde, mem, lengths);

    dim3 gridB(B_SZ / BM, D_SZ / BN);   // 64 x 2
    gate_gemm_bf16<<<gridB, 256>>>(h_tilde, Wg_b, Ug_b, b_g, lengths, out);
}

// round 5
// speedup vs baseline: 1.8946x; 1.2686x over previous
#include <cuda_runtime.h>
#include <cuda_bf16.h>
#include <cstdint>

#define B_SZ 8192
#define M_SZ 64
#define D_SZ 256
#define K1   1024   // Xc layout: [h_hi | r_hi | h_lo | r_lo]
#define K2   1536   // Wc layout: [W_hi | W_lo | W_hi]

// scratch (static device arrays — no allocation)
__device__ __align__(256) float          g_r[B_SZ * D_SZ];              // 8 MB
__device__ __align__(256) __nv_bfloat16  g_Xc[(size_t)B_SZ * K1];       // 16 MB
__device__ __align__(256) __nv_bfloat16  g_Wc[256 * K2];                // 768 KB

// ---------------------------------------------------------------------------
// cp.async helpers
// ---------------------------------------------------------------------------
__device__ __forceinline__ void cp_async16(void* smem_ptr, const void* gptr) {
    unsigned sa = (unsigned)__cvta_generic_to_shared(smem_ptr);
    asm volatile("cp.async.cg.shared.global [%0], [%1], 16;\n" :: "r"(sa), "l"(gptr));
}
__device__ __forceinline__ void cp_commit() {
    asm volatile("cp.async.commit_group;\n");
}
template<int N> __device__ __forceinline__ void cp_wait() {
    asm volatile("cp.async.wait_group %0;\n" :: "n"(N));
}

// ---------------------------------------------------------------------------
// Kernel A: ragged attention, ONLY valid chunks are loaded from HBM.
// CH=8 rows/chunk, 3-stage cp.async pipeline, 24KB smem -> 8 CTAs/SM.
// Per-thread (redundant) online softmax: no warp0 serialization.
// ---------------------------------------------------------------------------
#define CH 8
#define NST 3

__global__ __launch_bounds__(256, 8)
void attn_r_kernel(const float* __restrict__ h_tilde,
                   const float* __restrict__ mem,
                   const int* __restrict__ lengths) {
    __shared__ __align__(16) float buf[NST][CH * D_SZ];   // 3 x 8 KB
    __shared__ float s_h[D_SZ];
    __shared__ float s_sc[CH];

    const int b    = blockIdx.x;
    const int tid  = threadIdx.x;
    const int warp = tid >> 5;
    const int lane = tid & 31;
    const int len  = lengths[b];

    const float hv = h_tilde[(size_t)b * D_SZ + tid];
    s_h[tid] = hv;

    const int nch = (len + CH - 1) / CH;   // chunks actually needed
    float r = 0.f;

    if (len > 0) {
        const float* gm = mem + (size_t)b * M_SZ * D_SZ;

        // prime the pipeline: up to 3 chunks, one group each (groups are
        // committed unconditionally so group<->chunk numbering is static)
#pragma unroll
        for (int p = 0; p < NST; ++p) {
            if (p < nch) {
                const float4* g4 = (const float4*)(gm + p * CH * D_SZ);
                float4* s4 = (float4*)buf[p];
                cp_async16(s4 + tid, g4 + tid);
                cp_async16(s4 + tid + 256, g4 + tid + 256);
            }
            cp_commit();
        }

        float racc = 0.f;
        float Mrun = -3.0e38f;
        float Srun = 0.f;

        for (int c = 0; c < nch; ++c) {
            cp_wait<2>();          // group c (== chunk c) has landed
            __syncthreads();       // visible to all threads; prev reads done

            const float* bm = buf[c % NST];

            // scores: warp w owns local row w
            {
                const float* row = bm + warp * D_SZ;
                float acc = 0.f;
#pragma unroll
                for (int k = 0; k < 8; ++k)
                    acc = fmaf(row[lane + 32 * k], s_h[lane + 32 * k], acc);
#pragma unroll
                for (int off = 16; off; off >>= 1)
                    acc += __shfl_xor_sync(0xffffffffu, acc, off);
                if (lane == 0)
                    s_sc[warp] = (c * CH + warp < len) ? acc : -1e9f;
            }
            __syncthreads();

            // per-thread redundant online-softmax update + column accum
            float cmax = s_sc[0];
#pragma unroll
            for (int i = 1; i < CH; ++i) cmax = fmaxf(cmax, s_sc[i]);
            const float nM   = fmaxf(Mrun, cmax);
            const float corr = __expf(Mrun - nM);
            float csum = 0.f, acc2 = 0.f;
#pragma unroll
            for (int i = 0; i < CH; ++i) {
                const float e = __expf(s_sc[i] - nM);
                csum += e;
                acc2 = fmaf(e, bm[i * D_SZ + tid], acc2);
            }
            Srun = Srun * corr + csum;
            Mrun = nM;
            racc = racc * corr + acc2;
            __syncthreads();       // all reads of buf[c%NST] done

            const int pc = c + NST;
            if (pc < nch) {
                const float4* g4 = (const float4*)(gm + pc * CH * D_SZ);
                float4* s4 = (float4*)buf[c % NST];
                cp_async16(s4 + tid, g4 + tid);
                cp_async16(s4 + tid + 256, g4 + tid + 256);
            }
            cp_commit();
        }
        r = racc / Srun;
    }

    g_r[(size_t)b * D_SZ + tid] = r;

    // Xc row: [h_hi | r_hi | h_lo | r_lo]
    const __nv_bfloat16 hh = __float2bfloat16_rn(hv);
    const __nv_bfloat16 hl = __float2bfloat16_rn(hv - __bfloat162float(hh));
    const __nv_bfloat16 rh = __float2bfloat16_rn(r);
    const __nv_bfloat16 rl = __float2bfloat16_rn(r - __bfloat162float(rh));
    __nv_bfloat16* xr = g_Xc + (size_t)b * K1;
    xr[tid]       = hh;
    xr[256 + tid] = rh;
    xr[512 + tid] = hl;
    xr[768 + tid] = rl;
}

// ---------------------------------------------------------------------------
// W conversion: Wc[n] = [hi(W) | lo(W) | hi(W)], W[n] = [Wg_w[n] | Ug_w[n]]
// ---------------------------------------------------------------------------
__global__ void conv_w_kernel(const float* __restrict__ Wg_w,
                              const float* __restrict__ Ug_w) {
    const int n   = blockIdx.x / 6;
    const int j   = (blockIdx.x % 6) * 256 + threadIdx.x;
    const int k   = j & 511;
    const int seg = j >> 9;
    const float w = (k < 256) ? Wg_w[n * 256 + k] : Ug_w[n * 256 + (k - 256)];
    const __nv_bfloat16 hi = __float2bfloat16_rn(w);
    const __nv_bfloat16 v  = (seg == 1)
        ? __float2bfloat16_rn(w - __bfloat162float(hi))
        : hi;
    g_Wc[n * K2 + j] = v;
}

// ---------------------------------------------------------------------------
// Kernel B: bf16 tensor-core GEMM (virtual K=1536, A hi-segment reused) +
// fused sigmoid/gate/mask epilogue. BM=128, BN=128, BK=32, 256 threads.
// ---------------------------------------------------------------------------
#define BM 128
#define BN 128
#define BK 32
#define LDSK 40   // bf16 elems per smem row (80 B) — conflict-free

__device__ __forceinline__ void mma16816(float c[4], const uint32_t a[4],
                                         const uint32_t bq[2]) {
    asm volatile(
        "mma.sync.aligned.m16n8k16.row.col.f32.bf16.bf16.f32 "
        "{%0,%1,%2,%3}, {%4,%5,%6,%7}, {%8,%9}, {%0,%1,%2,%3};\n"
        : "+f"(c[0]), "+f"(c[1]), "+f"(c[2]), "+f"(c[3])
        : "r"(a[0]), "r"(a[1]), "r"(a[2]), "r"(a[3]), "r"(bq[0]), "r"(bq[1]));
}

// A-segment k-offset for virtual k-tile kt (BK=32):
//  kt 0..15  -> Xc[0:512)   (hi)   * W_hi
//  kt 16..31 -> Xc[0:512)   (hi)   * W_lo
//  kt 32..47 -> Xc[512:1024)(lo)   * W_hi
__device__ __forceinline__ int a_koff(int kt) {
    return (kt < 16) ? kt * BK : (kt < 32) ? (kt - 16) * BK
                                           : 512 + (kt - 32) * BK;
}

__global__ __launch_bounds__(256)
void gate_gemm_bf16(const float* __restrict__ h_tilde,
                    const float* __restrict__ Wg_b,
                    const float* __restrict__ Ug_b,
                    const float* __restrict__ b_g,
                    const int* __restrict__ lengths,
                    float* __restrict__ out) {
    __shared__ __align__(16) __nv_bfloat16 sA[2][BM * LDSK];
    __shared__ __align__(16) __nv_bfloat16 sB[2][BN * LDSK];

    const int tid  = threadIdx.x;
    const int warp = tid >> 5;
    const int lane = tid & 31;
    const int g    = lane >> 2;
    const int t    = lane & 3;
    const int wm   = warp >> 1;       // 0..3
    const int wn   = warp & 1;        // 0..1
    const int bm0  = blockIdx.x * BM;
    const int bn0  = blockIdx.y * BN;

    float acc[2][8][4];
#pragma unroll
    for (int mt = 0; mt < 2; ++mt)
#pragma unroll
        for (int nt = 0; nt < 8; ++nt)
#pragma unroll
            for (int i = 0; i < 4; ++i) acc[mt][nt][i] = 0.f;

    const __nv_bfloat16* gA = g_Xc + (size_t)bm0 * K1;
    const __nv_bfloat16* gB = g_Wc + (size_t)bn0 * K2;

    const int c0r = tid >> 2,         c0c = tid & 3;
    const int c1r = (tid + 256) >> 2, c1c = tid & 3;

    // prefetch stage 0 (kt=0: aoff=0, boff=0)
    {
        cp_async16(&sA[0][c0r * LDSK + c0c * 8], gA + (size_t)c0r * K1 + c0c * 8);
        cp_async16(&sB[0][c0r * LDSK + c0c * 8], gB + (size_t)c0r * K2 + c0c * 8);
        cp_async16(&sA[0][c1r * LDSK + c1c * 8], gA + (size_t)c1r * K1 + c1c * 8);
        cp_async16(&sB[0][c1r * LDSK + c1c * 8], gB + (size_t)c1r * K2 + c1c * 8);
        cp_commit();
    }

    const int NKT = K2 / BK;   // 48 virtual k-tiles
    for (int kt = 0; kt < NKT; ++kt) {
        __syncthreads();
        if (kt + 1 < NKT) {
            const int ao = a_koff(kt + 1);
            const int bo = (kt + 1) * BK;
            const int st = (kt + 1) & 1;
            cp_async16(&sA[st][c0r * LDSK + c0c * 8], gA + (size_t)c0r * K1 + ao + c0c * 8);
            cp_async16(&sB[st][c0r * LDSK + c0c * 8], gB + (size_t)c0r * K2 + bo + c0c * 8);
            cp_async16(&sA[st][c1r * LDSK + c1c * 8], gA + (size_t)c1r * K1 + ao + c1c * 8);
            cp_async16(&sB[st][c1r * LDSK + c1c * 8], gB + (size_t)c1r * K2 + bo + c1c * 8);
            cp_commit();
            cp_wait<1>();
        } else {
            cp_wait<0>();
        }
        __syncthreads();

        const __nv_bfloat16* A  = sA[kt & 1];
        const __nv_bfloat16* Bs = sB[kt & 1];

#pragma unroll
        for (int ks = 0; ks < 2; ++ks) {
            uint32_t af[2][4], bq[8][2];
#pragma unroll
            for (int mt = 0; mt < 2; ++mt) {
                const int idx0 = (wm * 32 + mt * 16 + g) * LDSK + ks * 16 + 2 * t;
                af[mt][0] = *(const uint32_t*)(A + idx0);
                af[mt][1] = *(const uint32_t*)(A + idx0 + 8 * LDSK);
                af[mt][2] = *(const uint32_t*)(A + idx0 + 8);
                af[mt][3] = *(const uint32_t*)(A + idx0 + 8 * LDSK + 8);
            }
#pragma unroll
            for (int nt = 0; nt < 8; ++nt) {
                const int idx = (wn * 64 + nt * 8 + g) * LDSK + ks * 16 + 2 * t;
                bq[nt][0] = *(const uint32_t*)(Bs + idx);
                bq[nt][1] = *(const uint32_t*)(Bs + idx + 8);
            }
#pragma unroll
            for (int mt = 0; mt < 2; ++mt)
#pragma unroll
                for (int nt = 0; nt < 8; ++nt)
                    mma16816(acc[mt][nt], af[mt], bq[nt]);
        }
    }

    // fused epilogue
#pragma unroll
    for (int nt = 0; nt < 8; ++nt) {
        const int n = bn0 + wn * 64 + nt * 8 + 2 * t;
        const float bi0 = Wg_b[n] + Ug_b[n] + b_g[n];
        const float bi1 = Wg_b[n + 1] + Ug_b[n + 1] + b_g[n + 1];
#pragma unroll
        for (int mt = 0; mt < 2; ++mt) {
#pragma unroll
            for (int h2 = 0; h2 < 2; ++h2) {
                const int row = bm0 + wm * 32 + mt * 16 + g + 8 * h2;
                const bool has = lengths[row] > 0;
                const size_t base = (size_t)row * D_SZ + n;
                const float2 rv = *(const float2*)(g_r + base);
                const float2 hv = *(const float2*)(h_tilde + base);
                const float z0 = acc[mt][nt][2 * h2 + 0] + bi0;
                const float z1 = acc[mt][nt][2 * h2 + 1] + bi1;
                const float g0 = 1.f / (1.f + __expf(-z0));
                const float g1 = 1.f / (1.f + __expf(-z1));
                const float o0 = has ? (g0 * rv.x + (1.f - g0) * hv.x) : hv.x;
                const float o1 = has ? (g1 * rv.y + (1.f - g1) * hv.y) : hv.y;
                *(float2*)(out + base) = make_float2(o0, o1);
            }
        }
    }
}

// ---------------------------------------------------------------------------
extern "C" void kernel_launch(void* const* d_in, const int* in_sizes, int n_in,
                              void* d_out, int out_size) {
    const float* h_tilde = (const float*)d_in[0];
    const float* mem     = (const float*)d_in[1];
    const int*   lengths = (const int*)d_in[2];
    const float* Wg_w    = (const float*)d_in[3];
    const float* Wg_b    = (const float*)d_in[4];
    const float* Ug_w    = (const float*)d_in[5];
    const float* Ug_b    = (const float*)d_in[6];
    const float* b_g     = (const float*)d_in[7];
    float* out = (float*)d_out;

    conv_w_kernel<<<1536, 256>>>(Wg_w, Ug_w);
    attn_r_kernel<<<B_SZ, 256>>>(h_tilde, mem, lengths);

    dim3 gridB(B_SZ / BM, D_SZ / BN);   // 64 x 2
    gate_gemm_bf16<<<gridB, 256>>>(h_tilde, Wg_b, Ug_b, b_g, lengths, out);
}